// round 13
// baseline (speedup 1.0000x reference)
#include <cuda_runtime.h>
#include <cuda_bf16.h>
#include <cstdint>

#define NB   8
#define CCH  256
#define SP   4096
#define NROW 32768
#define KCB  1024

#define ZQ_SIZE   8388608
#define LOSS_OFF  8388608
#define PERP_OFF  8388609
#define IDX_OFF   8388610
#define FULL_OUT  8421378

__device__ float  g_S[NROW];
__device__ float  g_esq[KCB];
__device__ int    g_idx[NROW];
__device__ int    g_counts[KCB];
__device__ double g_losspart[1024];
__device__ __nv_bfloat16 g_ebf[KCB * CCH];     // bf16 codebook (prep-converted)
__device__ unsigned short g_candk[NROW * 16];  // shortlist per row
__device__ unsigned char  g_candn[NROW];       // count (17 = overflow)

__device__ __forceinline__ uint32_t smem_u32(const void* p) {
    uint32_t a;
    asm("{ .reg .u64 t; cvta.to.shared.u64 t, %1; cvt.u32.u64 %0, t; }"
        : "=r"(a) : "l"(p));
    return a;
}
__device__ __forceinline__ unsigned fkey(float f) {
    unsigned u = __float_as_uint(f);
    return (u & 0x80000000u) ? ~u : (u | 0x80000000u);
}
__device__ __forceinline__ float finv(unsigned k) {
    unsigned u = (k & 0x80000000u) ? (k & 0x7FFFFFFFu) : ~k;
    return __uint_as_float(u);
}

// ---------------------------------------------------------------------------
// Kernel A: |z|^2 per row, |e|^2 per code, bf16 codebook, zero counts
// ---------------------------------------------------------------------------
__global__ void prep_kernel(const float* __restrict__ z,
                            const float* __restrict__ emb) {
    int bi  = blockIdx.x;
    int tid = threadIdx.x;
    if (bi < 128) {
        int n0 = bi * 256;
        int b  = n0 >> 12;
        int s  = (n0 & 4095) + tid;
        const float* zb = z + (size_t)b * CCH * SP + s;
        float acc = 0.f;
        #pragma unroll 8
        for (int c = 0; c < CCH; c++) {
            float v = zb[(size_t)c * SP];
            acc = __fmaf_rn(v, v, acc);
        }
        g_S[n0 + tid] = acc;
    } else if (bi < 132) {
        int k = (bi - 128) * 256 + tid;
        const float* er = emb + (size_t)k * CCH;
        float acc = 0.f;
        #pragma unroll 8
        for (int c = 0; c < CCH; c++) {
            float v = er[c];
            acc = __fmaf_rn(v, v, acc);
            g_ebf[(size_t)k * CCH + c] = __float2bfloat16(v);
        }
        g_esq[k] = acc;
    } else {
        for (int k = tid; k < KCB; k += 256) g_counts[k] = 0;
    }
}

// ---------------------------------------------------------------------------
// Kernel B: bf16 HMMA approximate filter + shortlist
//   A tile: z as [c][s] bf16, pitch 136 (conflict-free stores AND trans-ldmatrix)
//   B tile: codes [n][k] bf16, pitch 264 (non-trans ldmatrix, conflict-free)
//   t = esq - 2m (S dropped: per-row constant). MARGIN covers bf16 error whp.
// ---------------------------------------------------------------------------
#define APITCH 136
#define BPITCH 264
#define MARGIN 5.0e-3f
#define OFF_B     69632                 // A = 256*136*2
#define OFF_ESQ   103424                // B = 64*264*2 = 33792
#define OFF_BESTU 103680
#define OFF_CCNT  104192
#define OFF_CAND  104704
#define ARG_SMEM  108800

__global__ __launch_bounds__(256, 2)
void argmin_tc_kernel(const float* __restrict__ z) {
    extern __shared__ __align__(16) unsigned char sm[];
    __nv_bfloat16* As    = (__nv_bfloat16*)sm;
    __nv_bfloat16* Bs    = (__nv_bfloat16*)(sm + OFF_B);
    float*          esqs = (float*)(sm + OFF_ESQ);
    unsigned*       bestu= (unsigned*)(sm + OFF_BESTU);
    unsigned*       ccnt = (unsigned*)(sm + OFF_CCNT);
    unsigned short* cand = (unsigned short*)(sm + OFF_CAND);

    int tid = threadIdx.x;
    int n0  = blockIdx.x * 128;
    int b   = n0 >> 12;
    int s0  = n0 & 4095;
    const float* zb = z + (size_t)b * CCH * SP + s0;

    if (tid < 128) { bestu[tid] = 0xFF800000u; ccnt[tid] = 0; }  // key(+inf)

    // stage A channel-major: warp writes one contiguous 256B c-row per step
    {
        int c8 = tid >> 5, sq = tid & 31;
        #pragma unroll 4
        for (int p = 0; p < 32; p++) {
            int c = p * 8 + c8;
            float4 v = *(const float4*)(zb + (size_t)c * SP + 4 * sq);
            __nv_bfloat162 lo = __floats2bfloat162_rn(v.x, v.y);
            __nv_bfloat162 hi = __floats2bfloat162_rn(v.z, v.w);
            uint2 w;
            w.x = *(uint32_t*)&lo;
            w.y = *(uint32_t*)&hi;
            *(uint2*)(As + c * APITCH + 4 * sq) = w;
        }
    }

    uint32_t sb   = smem_u32(sm);
    int lane = tid & 31, warp = tid >> 5;
    int srow = warp * 16;
    int g = lane >> 2, q = lane & 3;
    // A (trans): lane supplies address of c-row segment; c_off = (l&7)+((l&16)>>1),
    // s segment base = srow + (l&8)
    uint32_t aoff = (uint32_t)(((((lane & 7) + ((lane & 16) >> 1)) * APITCH)
                               + srow + (lane & 8)) * 2);
    // B (non-trans): row n = (l&7)+((l&16)>>1), k byte offset 16 for l&8
    uint32_t boff = (uint32_t)((((lane & 7) + ((lane & 16) >> 1)) * BPITCH) * 2
                               + ((lane & 8) ? 16 : 0));

    float d[8][4];

    for (int kc = 0; kc < 16; kc++) {
        __syncthreads();
        // stage B: 64 codes x 256 c bf16 from g_ebf (16B vectors, conflict-free)
        {
            const uint4* src = (const uint4*)(g_ebf + (size_t)(kc * 64) * CCH);
            #pragma unroll
            for (int it = 0; it < 8; it++) {
                int i = tid + 256 * it;
                int r = i >> 5, cq = i & 31;
                uint4 v = src[r * 32 + cq];
                *(uint4*)(Bs + r * BPITCH + cq * 8) = v;
            }
            if (tid < 64) esqs[tid] = g_esq[kc * 64 + tid];
        }
        __syncthreads();

        #pragma unroll
        for (int nt = 0; nt < 8; nt++)
            #pragma unroll
            for (int t = 0; t < 4; t++) d[nt][t] = 0.f;

        uint32_t abase = sb + aoff;
        uint32_t bbase = sb + OFF_B + boff;
        #pragma unroll
        for (int cs = 0; cs < 16; cs++) {
            uint32_t a0, a1, a2, a3;
            asm volatile("ldmatrix.sync.aligned.m8n8.x4.trans.shared.b16 {%0,%1,%2,%3}, [%4];"
                         : "=r"(a0), "=r"(a1), "=r"(a2), "=r"(a3)
                         : "r"(abase + (uint32_t)(cs * 16 * APITCH * 2)));
            #pragma unroll
            for (int jp = 0; jp < 4; jp++) {
                uint32_t b0, b1, b2, b3;
                asm volatile("ldmatrix.sync.aligned.m8n8.x4.shared.b16 {%0,%1,%2,%3}, [%4];"
                             : "=r"(b0), "=r"(b1), "=r"(b2), "=r"(b3)
                             : "r"(bbase + (uint32_t)(jp * 16 * BPITCH * 2) + cs * 32));
                asm volatile("mma.sync.aligned.m16n8k16.row.col.f32.bf16.bf16.f32 "
                             "{%0,%1,%2,%3},{%4,%5,%6,%7},{%8,%9},{%0,%1,%2,%3};"
                             : "+f"(d[2*jp][0]), "+f"(d[2*jp][1]),
                               "+f"(d[2*jp][2]), "+f"(d[2*jp][3])
                             : "r"(a0), "r"(a1), "r"(a2), "r"(a3), "r"(b0), "r"(b1));
                asm volatile("mma.sync.aligned.m16n8k16.row.col.f32.bf16.bf16.f32 "
                             "{%0,%1,%2,%3},{%4,%5,%6,%7},{%8,%9},{%0,%1,%2,%3};"
                             : "+f"(d[2*jp+1][0]), "+f"(d[2*jp+1][1]),
                               "+f"(d[2*jp+1][2]), "+f"(d[2*jp+1][3])
                             : "r"(a0), "r"(a1), "r"(a2), "r"(a3), "r"(b2), "r"(b3));
            }
        }

        // shortlist epilogue: rows r0=srow+g, r1=r0+8; cols 8*nt + 2q + t
        int r0 = srow + g, r1 = r0 + 8;
        float bv0 = finv(bestu[r0]);
        float bv1 = finv(bestu[r1]);
        #pragma unroll
        for (int nt = 0; nt < 8; nt++) {
            #pragma unroll
            for (int t = 0; t < 2; t++) {
                int kl = nt * 8 + 2 * q + t;
                int kg = kc * 64 + kl;
                float v0 = __fmaf_rn(-2.f, d[nt][t], esqs[kl]);
                if (v0 < bv0 + MARGIN) {
                    unsigned pos = atomicAdd(&ccnt[r0], 1u);
                    if (pos < 16) cand[r0 * 16 + pos] = (unsigned short)kg;
                    if (v0 < bv0) bv0 = v0;
                    atomicMin(&bestu[r0], fkey(v0));
                }
                float v1 = __fmaf_rn(-2.f, d[nt][2 + t], esqs[kl]);
                if (v1 < bv1 + MARGIN) {
                    unsigned pos = atomicAdd(&ccnt[r1], 1u);
                    if (pos < 16) cand[r1 * 16 + pos] = (unsigned short)kg;
                    if (v1 < bv1) bv1 = v1;
                    atomicMin(&bestu[r1], fkey(v1));
                }
            }
        }
    }

    __syncthreads();
    if (tid < 128) {
        unsigned c = ccnt[tid];
        int n = n0 + tid;
        g_candn[n] = (unsigned char)(c > 16 ? 17 : c);
        int m = c > 16 ? 16 : (int)c;
        for (int j = 0; j < m; j++)
            g_candk[(size_t)n * 16 + j] = cand[tid * 16 + j];
    }
}

// ---------------------------------------------------------------------------
// Kernel C: fused exact recheck + STE + counts + loss partials
// ---------------------------------------------------------------------------
#define F_ZT   0                 // float [256][33]
#define F_ES   33792             // float [32][257]
#define F_RED  66688             // double [256]
#define F_CAND 68736             // u16 [32][16]
#define F_CNT  69760             // int [32]
#define F_IDX  69888             // int [32]
#define FUSE_SMEM 70016

__global__ __launch_bounds__(256)
void fuse_kernel(const float* __restrict__ z,
                 const float* __restrict__ emb,
                 float* __restrict__ out,
                 int has_extras) {
    extern __shared__ __align__(16) unsigned char sm[];
    float*          zt    = (float*)(sm + F_ZT);
    float*          es    = (float*)(sm + F_ES);
    double*         red   = (double*)(sm + F_RED);
    unsigned short* scand = (unsigned short*)(sm + F_CAND);
    int*            scnt  = (int*)(sm + F_CNT);
    int*            sidx  = (int*)(sm + F_IDX);

    int tid = threadIdx.x;
    int n0  = blockIdx.x * 32;
    int b   = n0 >> 12;
    int s0  = n0 & 4095;
    const float* zb = z + (size_t)b * CCH * SP + s0;

    // stage z tile [256 c][32 s]
    {
        int c8 = tid >> 5, s = tid & 31;
        for (int p = 0; p < 32; p++) {
            int c = p * 8 + c8;
            zt[c * 33 + s] = zb[(size_t)c * SP + s];
        }
    }
    if (tid < 32) scnt[tid] = g_candn[n0 + tid];
    for (int i = tid; i < 32 * 16; i += 256)
        scand[i] = g_candk[(size_t)n0 * 16 + i];
    __syncthreads();

    // exact recheck: s = tid>>3 (row), cg = tid&7 (channel group of 32)
    {
        int s  = tid >> 3, cg = tid & 7;
        int n  = n0 + s;
        int cnt = scnt[s];
        unsigned segmask = 0xFFu << (tid & 24);
        if (cnt == 1) {
            if (cg == 0) { int k = scand[s * 16]; sidx[s] = k; g_idx[n] = k; }
        } else {
            float S = g_S[n];
            bool listed = (cnt >= 2 && cnt <= 16);
            int trips = listed ? cnt : KCB;
            unsigned long long bk = 0xFFFFFFFFFFFFFFFFULL;
            for (int i = 0; i < trips; i++) {
                int k = listed ? (int)scand[s * 16 + i] : i;
                const float4* e4 = (const float4*)(emb + (size_t)k * CCH);
                float p = 0.f;
                #pragma unroll
                for (int j4 = 0; j4 < 8; j4++) {
                    float4 ev = e4[cg * 8 + j4];
                    int c = cg * 32 + j4 * 4;
                    p = __fmaf_rn(zt[(c + 0) * 33 + s], ev.x, p);
                    p = __fmaf_rn(zt[(c + 1) * 33 + s], ev.y, p);
                    p = __fmaf_rn(zt[(c + 2) * 33 + s], ev.z, p);
                    p = __fmaf_rn(zt[(c + 3) * 33 + s], ev.w, p);
                }
                p += __shfl_down_sync(segmask, p, 4, 8);
                p += __shfl_down_sync(segmask, p, 2, 8);
                p += __shfl_down_sync(segmask, p, 1, 8);
                if (cg == 0) {
                    float t = __fadd_rn(S, g_esq[k]);
                    float v = __fmaf_rn(-2.f, p, t);
                    unsigned long long key =
                        ((unsigned long long)fkey(v) << 32) | (unsigned)k;
                    if (key < bk) bk = key;
                }
            }
            if (cg == 0) {
                int k = (int)(bk & 0xFFFFFFFFu);
                sidx[s] = k; g_idx[n] = k;
            }
        }
    }
    __syncthreads();

    // gather chosen embedding rows
    for (int i = tid; i < 32 * 64; i += 256) {
        int r = i >> 6, qq = i & 63;
        float4 v = *(const float4*)(emb + (size_t)sidx[r] * CCH + qq * 4);
        es[r * 257 + qq * 4 + 0] = v.x;
        es[r * 257 + qq * 4 + 1] = v.y;
        es[r * 257 + qq * 4 + 2] = v.z;
        es[r * 257 + qq * 4 + 3] = v.w;
    }
    if (tid < 32) atomicAdd(&g_counts[sidx[tid]], 1);
    __syncthreads();

    // STE + loss (R4-validated rounding recipe)
    int s  = tid & 31;
    int cb = tid >> 5;
    float* ob = out + (size_t)b * CCH * SP + s0;
    float lacc = 0.f;
    #pragma unroll 4
    for (int c0 = 0; c0 < CCH; c0 += 8) {
        int c = c0 + cb;
        float zv = zt[c * 33 + s];
        float ev = es[s * 257 + c];
        float dd = __fadd_rn(ev, -zv);
        lacc = __fmaf_rn(dd, dd, lacc);
        ob[(size_t)c * SP + s] = __fadd_rn(zv, dd);
    }
    if (has_extras && tid < 32)
        out[IDX_OFF + n0 + tid] = (float)sidx[tid];

    red[tid] = (double)lacc;
    __syncthreads();
    for (int off = 128; off > 0; off >>= 1) {
        if (tid < off) red[tid] += red[tid + off];
        __syncthreads();
    }
    if (tid == 0) g_losspart[blockIdx.x] = red[0];
}

// ---------------------------------------------------------------------------
// Kernel D: final loss + perplexity (unchanged, R4-validated)
// ---------------------------------------------------------------------------
__global__ __launch_bounds__(1024)
void finalize_kernel(float* __restrict__ out, int has_extras) {
    __shared__ double sd[1024];
    int tid = threadIdx.x;

    {
        int   cnt = g_counts[tid];
        float em  = (float)cnt * (1.0f / 32768.0f);
        float t   = em * logf(em + 1e-10f);
        sd[tid] = (double)t;
    }
    __syncthreads();
    for (int off = 512; off > 0; off >>= 1) {
        if (tid < off) sd[tid] += sd[tid + off];
        __syncthreads();
    }
    float perplexity = expf(-(float)sd[0]);
    __syncthreads();

    sd[tid] = g_losspart[tid];
    __syncthreads();
    for (int off = 512; off > 0; off >>= 1) {
        if (tid < off) sd[tid] += sd[tid + off];
        __syncthreads();
    }
    if (tid == 0 && has_extras) {
        double mean = sd[0] / (double)ZQ_SIZE;
        float  m    = (float)mean;
        float  loss = __fadd_rn(m, 0.25f * m);
        out[LOSS_OFF] = loss;
        out[PERP_OFF] = perplexity;
    }
}

// ---------------------------------------------------------------------------
extern "C" void kernel_launch(void* const* d_in, const int* in_sizes, int n_in,
                              void* d_out, int out_size) {
    const float* z   = (const float*)d_in[0];
    const float* emb = (const float*)d_in[1];
    float* out = (float*)d_out;
    int has_extras = (out_size >= FULL_OUT) ? 1 : 0;

    cudaFuncSetAttribute(argmin_tc_kernel,
                         cudaFuncAttributeMaxDynamicSharedMemorySize, ARG_SMEM);
    cudaFuncSetAttribute(fuse_kernel,
                         cudaFuncAttributeMaxDynamicSharedMemorySize, FUSE_SMEM);

    prep_kernel<<<133, 256>>>(z, emb);
    argmin_tc_kernel<<<NROW / 128, 256, ARG_SMEM>>>(z);
    fuse_kernel<<<NROW / 32, 256, FUSE_SMEM>>>(z, emb, out, has_extras);
    finalize_kernel<<<1, 1024>>>(out, has_extras);
}

// round 14
// speedup vs baseline: 11.5733x; 11.5733x over previous
#include <cuda_runtime.h>
#include <cuda_bf16.h>
#include <cstdint>

#define NB   8
#define CCH  256
#define SP   4096
#define NROW 32768
#define KCB  1024

#define ZQ_SIZE   8388608
#define LOSS_OFF  8388608
#define PERP_OFF  8388609
#define IDX_OFF   8388610
#define FULL_OUT  8421378

__device__ float  g_S[NROW];
__device__ float  g_esq[KCB];
__device__ int    g_idx[NROW];
__device__ int    g_counts[KCB];
__device__ double g_losspart[1024];
__device__ __nv_bfloat16 g_ebf[KCB * CCH];     // bf16 codebook (prep-converted)
__device__ unsigned short g_candk[NROW * 16];  // shortlist per row
__device__ unsigned char  g_candn[NROW];       // count (17 = overflow)

__device__ __forceinline__ uint32_t smem_u32(const void* p) {
    uint32_t a;
    asm("{ .reg .u64 t; cvta.to.shared.u64 t, %1; cvt.u32.u64 %0, t; }"
        : "=r"(a) : "l"(p));
    return a;
}
__device__ __forceinline__ unsigned fkey(float f) {
    unsigned u = __float_as_uint(f);
    return (u & 0x80000000u) ? ~u : (u | 0x80000000u);
}
__device__ __forceinline__ float finv(unsigned k) {
    unsigned u = (k & 0x80000000u) ? (k & 0x7FFFFFFFu) : ~k;
    return __uint_as_float(u);
}

// ---------------------------------------------------------------------------
// Kernel A: |z|^2 per row, |e|^2 per code, bf16 codebook, zero counts
// ---------------------------------------------------------------------------
__global__ void prep_kernel(const float* __restrict__ z,
                            const float* __restrict__ emb) {
    int bi  = blockIdx.x;
    int tid = threadIdx.x;
    if (bi < 128) {
        int n0 = bi * 256;
        int b  = n0 >> 12;
        int s  = (n0 & 4095) + tid;
        const float* zb = z + (size_t)b * CCH * SP + s;
        float acc = 0.f;
        #pragma unroll 8
        for (int c = 0; c < CCH; c++) {
            float v = zb[(size_t)c * SP];
            acc = __fmaf_rn(v, v, acc);
        }
        g_S[n0 + tid] = acc;
    } else if (bi < 132) {
        int k = (bi - 128) * 256 + tid;
        const float* er = emb + (size_t)k * CCH;
        float acc = 0.f;
        #pragma unroll 8
        for (int c = 0; c < CCH; c++) {
            float v = er[c];
            acc = __fmaf_rn(v, v, acc);
            g_ebf[(size_t)k * CCH + c] = __float2bfloat16(v);
        }
        g_esq[k] = acc;
    } else {
        for (int k = tid; k < KCB; k += 256) g_counts[k] = 0;
    }
}

// ---------------------------------------------------------------------------
// Kernel B: bf16 HMMA filter, TWO-PHASE shortlist
//   Phase 0: per-row global min of t = esq - 2m (chunk-local min, 1 atomicMin).
//   Phase 1: identical deterministic MMA sweep; append codes with
//            v <= gmin + MARGIN  (expected ~1.7 candidates/row).
//   A tile: z as [c][s] bf16 pitch 136 (conflict-free stores + trans ldmatrix)
//   B tile: codes [n][k] bf16 pitch 264 (non-trans ldmatrix, conflict-free)
// ---------------------------------------------------------------------------
#define APITCH 136
#define BPITCH 264
#define MARGIN 5.0e-3f
#define OFF_B     69632                 // A = 256*136*2
#define OFF_ESQ   103424                // B = 64*264*2 = 33792
#define OFF_BESTU 103680
#define OFF_CCNT  104192
#define OFF_CAND  104704
#define ARG_SMEM  108800

__global__ __launch_bounds__(256, 2)
void argmin_tc_kernel(const float* __restrict__ z) {
    extern __shared__ __align__(16) unsigned char sm[];
    __nv_bfloat16* As    = (__nv_bfloat16*)sm;
    __nv_bfloat16* Bs    = (__nv_bfloat16*)(sm + OFF_B);
    float*          esqs = (float*)(sm + OFF_ESQ);
    unsigned*       bestu= (unsigned*)(sm + OFF_BESTU);
    unsigned*       ccnt = (unsigned*)(sm + OFF_CCNT);
    unsigned short* cand = (unsigned short*)(sm + OFF_CAND);

    int tid = threadIdx.x;
    int n0  = blockIdx.x * 128;
    int b   = n0 >> 12;
    int s0  = n0 & 4095;
    const float* zb = z + (size_t)b * CCH * SP + s0;

    if (tid < 128) { bestu[tid] = 0xFF800000u; ccnt[tid] = 0; }  // key(+inf)

    // stage A channel-major: warp writes one contiguous 256B c-row per step
    {
        int c8 = tid >> 5, sq = tid & 31;
        #pragma unroll 4
        for (int p = 0; p < 32; p++) {
            int c = p * 8 + c8;
            float4 v = *(const float4*)(zb + (size_t)c * SP + 4 * sq);
            __nv_bfloat162 lo = __floats2bfloat162_rn(v.x, v.y);
            __nv_bfloat162 hi = __floats2bfloat162_rn(v.z, v.w);
            uint2 w;
            w.x = *(uint32_t*)&lo;
            w.y = *(uint32_t*)&hi;
            *(uint2*)(As + c * APITCH + 4 * sq) = w;
        }
    }

    uint32_t sb   = smem_u32(sm);
    int lane = tid & 31, warp = tid >> 5;
    int srow = warp * 16;
    int g = lane >> 2, q = lane & 3;
    int r0v = srow + g, r1v = r0v + 8;
    uint32_t aoff = (uint32_t)(((((lane & 7) + ((lane & 16) >> 1)) * APITCH)
                               + srow + (lane & 8)) * 2);
    uint32_t boff = (uint32_t)((((lane & 7) + ((lane & 16) >> 1)) * BPITCH) * 2
                               + ((lane & 8) ? 16 : 0));

    float d[8][4];

    for (int phase = 0; phase < 2; phase++) {
        float lim0 = 0.f, lim1 = 0.f;
        if (phase == 1) {
            __syncthreads();   // all phase-0 atomicMins visible
            lim0 = finv(bestu[r0v]) + MARGIN;
            lim1 = finv(bestu[r1v]) + MARGIN;
        }

        for (int kc = 0; kc < 16; kc++) {
            __syncthreads();
            // stage B: 64 codes x 256 c bf16 (16B vectors, conflict-free)
            {
                const uint4* src = (const uint4*)(g_ebf + (size_t)(kc * 64) * CCH);
                #pragma unroll
                for (int it = 0; it < 8; it++) {
                    int i = tid + 256 * it;
                    int r = i >> 5, cq = i & 31;
                    uint4 v = src[r * 32 + cq];
                    *(uint4*)(Bs + r * BPITCH + cq * 8) = v;
                }
                if (tid < 64) esqs[tid] = g_esq[kc * 64 + tid];
            }
            __syncthreads();

            #pragma unroll
            for (int nt = 0; nt < 8; nt++)
                #pragma unroll
                for (int t = 0; t < 4; t++) d[nt][t] = 0.f;

            uint32_t abase = sb + aoff;
            uint32_t bbase = sb + OFF_B + boff;
            #pragma unroll
            for (int cs = 0; cs < 16; cs++) {
                uint32_t a0, a1, a2, a3;
                asm volatile("ldmatrix.sync.aligned.m8n8.x4.trans.shared.b16 {%0,%1,%2,%3}, [%4];"
                             : "=r"(a0), "=r"(a1), "=r"(a2), "=r"(a3)
                             : "r"(abase + (uint32_t)(cs * 16 * APITCH * 2)));
                #pragma unroll
                for (int jp = 0; jp < 4; jp++) {
                    uint32_t b0, b1, b2, b3;
                    asm volatile("ldmatrix.sync.aligned.m8n8.x4.shared.b16 {%0,%1,%2,%3}, [%4];"
                                 : "=r"(b0), "=r"(b1), "=r"(b2), "=r"(b3)
                                 : "r"(bbase + (uint32_t)(jp * 16 * BPITCH * 2) + cs * 32));
                    asm volatile("mma.sync.aligned.m16n8k16.row.col.f32.bf16.bf16.f32 "
                                 "{%0,%1,%2,%3},{%4,%5,%6,%7},{%8,%9},{%0,%1,%2,%3};"
                                 : "+f"(d[2*jp][0]), "+f"(d[2*jp][1]),
                                   "+f"(d[2*jp][2]), "+f"(d[2*jp][3])
                                 : "r"(a0), "r"(a1), "r"(a2), "r"(a3), "r"(b0), "r"(b1));
                    asm volatile("mma.sync.aligned.m16n8k16.row.col.f32.bf16.bf16.f32 "
                                 "{%0,%1,%2,%3},{%4,%5,%6,%7},{%8,%9},{%0,%1,%2,%3};"
                                 : "+f"(d[2*jp+1][0]), "+f"(d[2*jp+1][1]),
                                   "+f"(d[2*jp+1][2]), "+f"(d[2*jp+1][3])
                                 : "r"(a0), "r"(a1), "r"(a2), "r"(a3), "r"(b2), "r"(b3));
                }
            }

            if (phase == 0) {
                // chunk-local mins, one atomicMin per row per thread
                float lm0 = __int_as_float(0x7f800000);
                float lm1 = __int_as_float(0x7f800000);
                #pragma unroll
                for (int nt = 0; nt < 8; nt++) {
                    #pragma unroll
                    for (int t = 0; t < 2; t++) {
                        int kl = nt * 8 + 2 * q + t;
                        float v0 = __fmaf_rn(-2.f, d[nt][t],     esqs[kl]);
                        float v1 = __fmaf_rn(-2.f, d[nt][2 + t], esqs[kl]);
                        if (v0 < lm0) lm0 = v0;
                        if (v1 < lm1) lm1 = v1;
                    }
                }
                atomicMin(&bestu[r0v], fkey(lm0));
                atomicMin(&bestu[r1v], fkey(lm1));
            } else {
                // append-only vs final min (rare hits)
                #pragma unroll
                for (int nt = 0; nt < 8; nt++) {
                    #pragma unroll
                    for (int t = 0; t < 2; t++) {
                        int kl = nt * 8 + 2 * q + t;
                        int kg = kc * 64 + kl;
                        float v0 = __fmaf_rn(-2.f, d[nt][t],     esqs[kl]);
                        if (v0 <= lim0) {
                            unsigned pos = atomicAdd(&ccnt[r0v], 1u);
                            if (pos < 16) cand[r0v * 16 + pos] = (unsigned short)kg;
                        }
                        float v1 = __fmaf_rn(-2.f, d[nt][2 + t], esqs[kl]);
                        if (v1 <= lim1) {
                            unsigned pos = atomicAdd(&ccnt[r1v], 1u);
                            if (pos < 16) cand[r1v * 16 + pos] = (unsigned short)kg;
                        }
                    }
                }
            }
        }
    }

    __syncthreads();
    if (tid < 128) {
        unsigned c = ccnt[tid];
        int n = n0 + tid;
        g_candn[n] = (unsigned char)(c > 16 ? 17 : c);
        int m = c > 16 ? 16 : (int)c;
        for (int j = 0; j < m; j++)
            g_candk[(size_t)n * 16 + j] = cand[tid * 16 + j];
    }
}

// ---------------------------------------------------------------------------
// Kernel C: fused exact recheck + STE + counts + loss partials
// ---------------------------------------------------------------------------
#define F_ZT   0                 // float [256][33]
#define F_ES   33792             // float [32][257]
#define F_RED  66688             // double [256]
#define F_CAND 68736             // u16 [32][16]
#define F_CNT  69760             // int [32]
#define F_IDX  69888             // int [32]
#define FUSE_SMEM 70016

__global__ __launch_bounds__(256)
void fuse_kernel(const float* __restrict__ z,
                 const float* __restrict__ emb,
                 float* __restrict__ out,
                 int has_extras) {
    extern __shared__ __align__(16) unsigned char sm[];
    float*          zt    = (float*)(sm + F_ZT);
    float*          es    = (float*)(sm + F_ES);
    double*         red   = (double*)(sm + F_RED);
    unsigned short* scand = (unsigned short*)(sm + F_CAND);
    int*            scnt  = (int*)(sm + F_CNT);
    int*            sidx  = (int*)(sm + F_IDX);

    int tid = threadIdx.x;
    int n0  = blockIdx.x * 32;
    int b   = n0 >> 12;
    int s0  = n0 & 4095;
    const float* zb = z + (size_t)b * CCH * SP + s0;

    // stage z tile [256 c][32 s]
    {
        int c8 = tid >> 5, s = tid & 31;
        for (int p = 0; p < 32; p++) {
            int c = p * 8 + c8;
            zt[c * 33 + s] = zb[(size_t)c * SP + s];
        }
    }
    if (tid < 32) scnt[tid] = g_candn[n0 + tid];
    for (int i = tid; i < 32 * 16; i += 256)
        scand[i] = g_candk[(size_t)n0 * 16 + i];
    __syncthreads();

    // exact recheck: s = tid>>3 (row), cg = tid&7 (channel group of 32)
    {
        int s  = tid >> 3, cg = tid & 7;
        int n  = n0 + s;
        int cnt = scnt[s];
        unsigned segmask = 0xFFu << (tid & 24);
        if (cnt == 1) {
            if (cg == 0) { int k = scand[s * 16]; sidx[s] = k; g_idx[n] = k; }
        } else {
            float S = g_S[n];
            bool listed = (cnt >= 2 && cnt <= 16);
            int trips = listed ? cnt : KCB;
            unsigned long long bk = 0xFFFFFFFFFFFFFFFFULL;
            for (int i = 0; i < trips; i++) {
                int k = listed ? (int)scand[s * 16 + i] : i;
                const float4* e4 = (const float4*)(emb + (size_t)k * CCH);
                float p = 0.f;
                #pragma unroll
                for (int j4 = 0; j4 < 8; j4++) {
                    float4 ev = e4[cg * 8 + j4];
                    int c = cg * 32 + j4 * 4;
                    p = __fmaf_rn(zt[(c + 0) * 33 + s], ev.x, p);
                    p = __fmaf_rn(zt[(c + 1) * 33 + s], ev.y, p);
                    p = __fmaf_rn(zt[(c + 2) * 33 + s], ev.z, p);
                    p = __fmaf_rn(zt[(c + 3) * 33 + s], ev.w, p);
                }
                p += __shfl_down_sync(segmask, p, 4, 8);
                p += __shfl_down_sync(segmask, p, 2, 8);
                p += __shfl_down_sync(segmask, p, 1, 8);
                if (cg == 0) {
                    float t = __fadd_rn(S, g_esq[k]);
                    float v = __fmaf_rn(-2.f, p, t);
                    unsigned long long key =
                        ((unsigned long long)fkey(v) << 32) | (unsigned)k;
                    if (key < bk) bk = key;
                }
            }
            if (cg == 0) {
                int k = (int)(bk & 0xFFFFFFFFu);
                sidx[s] = k; g_idx[n] = k;
            }
        }
    }
    __syncthreads();

    // gather chosen embedding rows
    for (int i = tid; i < 32 * 64; i += 256) {
        int r = i >> 6, qq = i & 63;
        float4 v = *(const float4*)(emb + (size_t)sidx[r] * CCH + qq * 4);
        es[r * 257 + qq * 4 + 0] = v.x;
        es[r * 257 + qq * 4 + 1] = v.y;
        es[r * 257 + qq * 4 + 2] = v.z;
        es[r * 257 + qq * 4 + 3] = v.w;
    }
    if (tid < 32) atomicAdd(&g_counts[sidx[tid]], 1);
    __syncthreads();

    // STE + loss (R4-validated rounding recipe)
    int s  = tid & 31;
    int cb = tid >> 5;
    float* ob = out + (size_t)b * CCH * SP + s0;
    float lacc = 0.f;
    #pragma unroll 4
    for (int c0 = 0; c0 < CCH; c0 += 8) {
        int c = c0 + cb;
        float zv = zt[c * 33 + s];
        float ev = es[s * 257 + c];
        float dd = __fadd_rn(ev, -zv);
        lacc = __fmaf_rn(dd, dd, lacc);
        ob[(size_t)c * SP + s] = __fadd_rn(zv, dd);
    }
    if (has_extras && tid < 32)
        out[IDX_OFF + n0 + tid] = (float)sidx[tid];

    red[tid] = (double)lacc;
    __syncthreads();
    for (int off = 128; off > 0; off >>= 1) {
        if (tid < off) red[tid] += red[tid + off];
        __syncthreads();
    }
    if (tid == 0) g_losspart[blockIdx.x] = red[0];
}

// ---------------------------------------------------------------------------
// Kernel D: final loss + perplexity (unchanged, R4-validated)
// ---------------------------------------------------------------------------
__global__ __launch_bounds__(1024)
void finalize_kernel(float* __restrict__ out, int has_extras) {
    __shared__ double sd[1024];
    int tid = threadIdx.x;

    {
        int   cnt = g_counts[tid];
        float em  = (float)cnt * (1.0f / 32768.0f);
        float t   = em * logf(em + 1e-10f);
        sd[tid] = (double)t;
    }
    __syncthreads();
    for (int off = 512; off > 0; off >>= 1) {
        if (tid < off) sd[tid] += sd[tid + off];
        __syncthreads();
    }
    float perplexity = expf(-(float)sd[0]);
    __syncthreads();

    sd[tid] = g_losspart[tid];
    __syncthreads();
    for (int off = 512; off > 0; off >>= 1) {
        if (tid < off) sd[tid] += sd[tid + off];
        __syncthreads();
    }
    if (tid == 0 && has_extras) {
        double mean = sd[0] / (double)ZQ_SIZE;
        float  m    = (float)mean;
        float  loss = __fadd_rn(m, 0.25f * m);
        out[LOSS_OFF] = loss;
        out[PERP_OFF] = perplexity;
    }
}

// ---------------------------------------------------------------------------
extern "C" void kernel_launch(void* const* d_in, const int* in_sizes, int n_in,
                              void* d_out, int out_size) {
    const float* z   = (const float*)d_in[0];
    const float* emb = (const float*)d_in[1];
    float* out = (float*)d_out;
    int has_extras = (out_size >= FULL_OUT) ? 1 : 0;

    cudaFuncSetAttribute(argmin_tc_kernel,
                         cudaFuncAttributeMaxDynamicSharedMemorySize, ARG_SMEM);
    cudaFuncSetAttribute(fuse_kernel,
                         cudaFuncAttributeMaxDynamicSharedMemorySize, FUSE_SMEM);

    prep_kernel<<<133, 256>>>(z, emb);
    argmin_tc_kernel<<<NROW / 128, 256, ARG_SMEM>>>(z);
    fuse_kernel<<<NROW / 32, 256, FUSE_SMEM>>>(z, emb, out, has_extras);
    finalize_kernel<<<1, 1024>>>(out, has_extras);
}